// round 12
// baseline (speedup 1.0000x reference)
#include <cuda_runtime.h>
#include <cstdint>

#define N_  2
#define T_  2048
#define D_  512
#define H_  8
#define HD_ 64
#define NTD (N_*T_*D_)
#define NHTHD (N_*H_*T_*HD_)

// Scratch: [stream][q/k/v][n,h,t,hd], values pre-rounded to tf32 (rna)
__device__ float g_buf[2][3][NHTHD];
__device__ float g_sc[2][H_*HD_];
// p scratch: [blk(1024)][rq(4)][t(64)][kh*64 + j*32 + lane] float4 (A-frag layout)
__device__ float4 g_p[1024u*4u*64u*128u];

// attn smem word offsets
#define QP 0                    // Q A-frags: 32 groups * 132 = 4224 words
                                // (after pass 1: zt at 0..127, izt at 128..191)
#define TB 4224                 // tile double-buffer, 4096 words per buf
#define TBSTRIDE 4096
#define SMEM_WORDS (4224 + 2*4096)   // 12416 words = 49664 B

// ---------------------------------------------------------------------------
__global__ void scale_kernel(const float* __restrict__ isc,
                             const float* __restrict__ lsc) {
    int i = threadIdx.x;
    if (i >= 16) return;
    int s = i >> 3, h = i & 7;
    const float* src = (s == 0 ? isc : lsc) + h * HD_;
    float m = -1e30f;
    for (int d = 0; d < HD_; d++) m = fmaxf(m, src[d]);
    float Z = 0.f;
    for (int d = 0; d < HD_; d++) Z += __expf(src[d] - m);
    float inv = 1.f / Z;
    for (int d = 0; d < HD_; d++) g_sc[s][h*HD_ + d] = __expf(src[d] - m) * inv;
}

__device__ __forceinline__ uint32_t f2tf(float x) {
    uint32_t r;
    asm("cvt.rna.tf32.f32 %0, %1;" : "=r"(r) : "f"(x));
    return r;
}
__device__ __forceinline__ float tf32r(float x) { return __uint_as_float(f2tf(x)); }

__device__ __forceinline__ void mma_tf32(float (&d)[4],
                                         uint32_t a0, uint32_t a1, uint32_t a2, uint32_t a3,
                                         uint32_t b0, uint32_t b1) {
    asm volatile(
        "mma.sync.aligned.m16n8k8.row.col.f32.tf32.tf32.f32 "
        "{%0,%1,%2,%3}, {%4,%5,%6,%7}, {%8,%9}, {%0,%1,%2,%3};"
        : "+f"(d[0]), "+f"(d[1]), "+f"(d[2]), "+f"(d[3])
        : "r"(a0), "r"(a1), "r"(a2), "r"(a3), "r"(b0), "r"(b1));
}

// ---------------------------------------------------------------------------
// QKV projection, tf32 mma, 128(M) x 64(N) tiles, K=512, reg-prefetched.
// Both streams in one launch (blockIdx.z). Writes tf32-rounded fp32.
// ---------------------------------------------------------------------------
__global__ __launch_bounds__(256, 2)
void qkv_tf32_kernel(const float* __restrict__ x, const float* __restrict__ y,
                     const float* __restrict__ iw, const float* __restrict__ lw) {
    __shared__ uint32_t ap[4224];
    __shared__ uint32_t bp[2112];
    int stream = blockIdx.z;
    const float* z = stream ? y : x;
    const float* W = stream ? lw : iw;
    int tid = threadIdx.x;
    int w = tid >> 5, lane = tid & 31;
    int g = lane >> 2, c = lane & 3;
    int rq = w & 3, nh = w >> 2;
    int c0 = blockIdx.x * 64;
    int m0 = blockIdx.y * 128;

    float acc[2][4][4];
    #pragma unroll
    for (int a = 0; a < 2; a++)
        #pragma unroll
        for (int b = 0; b < 4; b++)
            #pragma unroll
            for (int e = 0; e < 4; e++) acc[a][b][e] = 0.f;

    float4 zr[4], wr[2];
    #pragma unroll
    for (int p = 0; p < 4; p++) {
        int i4 = tid + p * 256;
        zr[p] = *(const float4*)&z[(m0 + (i4 >> 3)) * 512 + (i4 & 7) * 4];
    }
    #pragma unroll
    for (int p = 0; p < 2; p++) {
        int i4 = tid + p * 256;
        wr[p] = *(const float4*)&W[(c0 + (i4 >> 3)) * 512 + (i4 & 7) * 4];
    }

    for (int it = 0; it < 16; it++) {
        __syncthreads();
        #pragma unroll
        for (int p = 0; p < 4; p++) {
            int i4 = tid + p * 256;
            int row = i4 >> 3, kq = i4 & 7;
            int base = ((row >> 4) * 4 + (kq >> 1)) * 132 + (row & 7) * 16
                     + (kq & 1) * 2 + ((row >> 3) & 1);
            ap[base + 0]  = f2tf(zr[p].x);
            ap[base + 4]  = f2tf(zr[p].y);
            ap[base + 8]  = f2tf(zr[p].z);
            ap[base + 12] = f2tf(zr[p].w);
        }
        #pragma unroll
        for (int p = 0; p < 2; p++) {
            int i4 = tid + p * 256;
            int col = i4 >> 3, kq = i4 & 7;
            int base = ((col >> 3) * 4 + (kq >> 1)) * 66 + (col & 7) * 8 + (kq & 1);
            bp[base + 0] = f2tf(wr[p].x);
            bp[base + 2] = f2tf(wr[p].y);
            bp[base + 4] = f2tf(wr[p].z);
            bp[base + 6] = f2tf(wr[p].w);
        }
        __syncthreads();
        if (it < 15) {
            int k0 = (it + 1) * 32;
            #pragma unroll
            for (int p = 0; p < 4; p++) {
                int i4 = tid + p * 256;
                zr[p] = *(const float4*)&z[(m0 + (i4 >> 3)) * 512 + k0 + (i4 & 7) * 4];
            }
            #pragma unroll
            for (int p = 0; p < 2; p++) {
                int i4 = tid + p * 256;
                wr[p] = *(const float4*)&W[(c0 + (i4 >> 3)) * 512 + k0 + (i4 & 7) * 4];
            }
        }
        #pragma unroll
        for (int ks = 0; ks < 4; ks++) {
            uint4 a0 = *(const uint4*)&ap[((rq * 2 + 0) * 4 + ks) * 132 + lane * 4];
            uint4 a1 = *(const uint4*)&ap[((rq * 2 + 1) * 4 + ks) * 132 + lane * 4];
            #pragma unroll
            for (int np = 0; np < 4; np++) {
                uint2 b = *(const uint2*)&bp[((nh * 4 + np) * 4 + ks) * 66 + lane * 2];
                mma_tf32(acc[0][np], a0.x, a0.y, a0.z, a0.w, b.x, b.y);
                mma_tf32(acc[1][np], a1.x, a1.y, a1.z, a1.w, b.x, b.y);
            }
        }
    }

    int three = c0 >> 9;
    int h = (c0 >> 6) & 7;
    float* dst = g_buf[stream][three];
    #pragma unroll
    for (int grp = 0; grp < 2; grp++) {
        #pragma unroll
        for (int np = 0; np < 4; np++) {
            int colb = nh * 32 + np * 8 + 2 * c;
            float sx = 1.f, sy = 1.f;
            if (three == 0) {
                float2 s2 = *(const float2*)&g_sc[stream][h * 64 + colb];
                sx = s2.x; sy = s2.y;
            }
            int m = m0 + rq * 32 + grp * 16 + g;
            int nn = m >> 11, t = m & 2047;
            *(float2*)&dst[((nn * 8 + h) * 2048 + t) * 64 + colb] =
                make_float2(tf32r(acc[grp][np][0] * sx), tf32r(acc[grp][np][1] * sy));
            int m2 = m + 8;
            int nn2 = m2 >> 11, t2 = m2 & 2047;
            *(float2*)&dst[((nn2 * 8 + h) * 2048 + t2) * 64 + colb] =
                make_float2(tf32r(acc[grp][np][2] * sx), tf32r(acc[grp][np][3] * sy));
        }
    }
}

// ---------------------------------------------------------------------------
// Dual attention. Block = (stream, n, h, 64-row q-tile), 8 warps, 3 CTAs/SM.
// No-max softmax (|S| <= ~1).
// Pass 1 (warp = 16 rows x 16 keys; rq=w&3, kh=w>>2): QK^T, partial Z,
//         p = exp(S) shuffled to A-frag layout, coalesced STG to g_p.
//         Z halves combined via smem, iZ table published.
// Pass 2 (warp = 16 rows x 32 dcols; rq=w&3, dh=w>>2): a = p*iZ,
//         w = exp(-a); two AV mmas vs Vc/Vf in swizzled smem.
// anti = softmax(max(attn)-attn) == softmax(-attn)
// ---------------------------------------------------------------------------
__global__ __launch_bounds__(256, 3)
void attn_kernel(const float* __restrict__ sp, float* __restrict__ out) {
    extern __shared__ uint32_t smu[];
    int tid = threadIdx.x;
    int w = tid >> 5, lane = tid & 31;
    int g = lane >> 2, c = lane & 3;
    int qt = blockIdx.x, h = blockIdx.y, zb = blockIdx.z;
    int s = zb >> 1, n = zb & 1;
    int blk = (zb * 8 + h) * 32 + qt;
    int rq = w & 3, kh = w >> 2;      // pass-1 roles (kh doubles as dh in pass 2)

    const float* Qb  = g_buf[s][0]     + ((n * H_ + h) * T_ + qt * 64) * HD_;
    const float* Kb  = g_buf[1 - s][1] + ((n * H_ + h) * T_) * HD_;
    const float* Vcb = g_buf[1 - s][2] + ((n * H_ + h) * T_) * HD_;
    const float* Vfb = g_buf[s][2]     + ((n * H_ + h) * T_) * HD_;
    float* ob = out + s * NTD;
    float spv = *sp;

    // stage Q [64x64] into A-frag layout once (values pre-rounded)
    #pragma unroll
    for (int p = 0; p < 4; p++) {
        int i4 = tid + p * 256;
        int row = i4 >> 4, kq = i4 & 15;
        float4 qv = *(const float4*)&Qb[row * 64 + kq * 4];
        int base = QP + ((row >> 4) * 8 + (kq >> 1)) * 132 + (row & 7) * 16
                 + (kq & 1) * 2 + ((row >> 3) & 1);
        smu[base + 0]  = __float_as_uint(qv.x);
        smu[base + 4]  = __float_as_uint(qv.y);
        smu[base + 8]  = __float_as_uint(qv.z);
        smu[base + 12] = __float_as_uint(qv.w);
    }
    __syncthreads();

    // pull this warp's Q A-frags (rows rq*16..+16) into registers
    uint4 qf[8];
    #pragma unroll
    for (int ks = 0; ks < 8; ks++)
        qf[ks] = *(const uint4*)&smu[QP + (rq * 8 + ks) * 132 + lane * 4];
    __syncthreads();   // qf read done before zt overwrites QP

    int srcA = (lane & ~3) | (c >> 1);
    int srcB = srcA + 2;
    bool odd = lane & 1;

    // ================= pass 1: partial Z, p -> gmem =========================
    float4 kreg[2];
    #pragma unroll
    for (int p = 0; p < 2; p++) {
        int i4 = tid + p * 256;
        kreg[p] = *(const float4*)&Kb[(i4 >> 4) * 64 + (i4 & 15) * 4];
    }

    float zs0 = 0.f, zs1 = 0.f;
    for (int t = 0; t < 64; t++) {
        uint32_t kb = TB + (t & 1) * TBSTRIDE;
        #pragma unroll
        for (int p = 0; p < 2; p++) {
            int i4 = tid + p * 256;
            int key = i4 >> 4, bk = i4 & 15;
            *(float4*)&smu[kb + key * 64 + ((bk ^ (key & 7)) << 2)] = kreg[p];
        }
        __syncthreads();
        if (t < 63) {
            #pragma unroll
            for (int p = 0; p < 2; p++) {
                int i4 = tid + p * 256;
                kreg[p] = *(const float4*)&Kb[(t + 1) * 2048 + (i4 >> 4) * 64 + (i4 & 15) * 4];
            }
        }
        float S[2][4];
        #pragma unroll
        for (int j = 0; j < 2; j++) { S[j][0]=0.f; S[j][1]=0.f; S[j][2]=0.f; S[j][3]=0.f; }
        #pragma unroll
        for (int ks = 0; ks < 8; ks++) {
            uint4 a = qf[ks];
            #pragma unroll
            for (int j = 0; j < 2; j++) {
                int jg = kh * 2 + j;
                uint32_t base = kb + (jg * 8 + g) * 64 + c;
                uint32_t b0 = smu[base + (((ks * 2) ^ g) << 2)];
                uint32_t b1 = smu[base + (((ks * 2 + 1) ^ g) << 2)];
                mma_tf32(S[j], a.x, a.y, a.z, a.w, b0, b1);
            }
        }
        // p = exp(S); Z partials; shuffle C-frag -> A-frag; coalesced STG
        float4* pg = &g_p[((blk * 4 + rq) * 64 + t) * 128 + kh * 64 + lane];
        #pragma unroll
        for (int j = 0; j < 2; j++) {
            float p0 = __expf(S[j][0]);
            float p1 = __expf(S[j][1]);
            float p2 = __expf(S[j][2]);
            float p3 = __expf(S[j][3]);
            zs0 += p0 + p1;
            zs1 += p2 + p3;
            float x0 = __shfl_sync(~0u, p0, srcA);
            float x1 = __shfl_sync(~0u, p1, srcA);
            float y0 = __shfl_sync(~0u, p2, srcA);
            float y1 = __shfl_sync(~0u, p3, srcA);
            float u0 = __shfl_sync(~0u, p0, srcB);
            float u1 = __shfl_sync(~0u, p1, srcB);
            float v0 = __shfl_sync(~0u, p2, srcB);
            float v1 = __shfl_sync(~0u, p3, srcB);
            float4 o;
            o.x = odd ? x1 : x0;   // a0: row g,   key c
            o.y = odd ? y1 : y0;   // a1: row g+8, key c
            o.z = odd ? u1 : u0;   // a2: row g,   key c+4
            o.w = odd ? v1 : v0;   // a3: row g+8, key c+4
            pg[j * 32] = o;
        }
    }
    zs0 += __shfl_xor_sync(~0u, zs0, 1);
    zs0 += __shfl_xor_sync(~0u, zs0, 2);
    zs1 += __shfl_xor_sync(~0u, zs1, 1);
    zs1 += __shfl_xor_sync(~0u, zs1, 2);

    // combine Z key-halves via smem: zt[kh*64 + rq*16 + row], izt at +128
    float* zt = (float*)smu;
    if (c == 0) {
        zt[kh * 64 + rq * 16 + g]     = zs0;
        zt[kh * 64 + rq * 16 + g + 8] = zs1;
    }
    __syncthreads();
    float* izt = zt + 128;
    if (tid < 64) izt[tid] = 1.f / (zt[tid] + zt[64 + tid]);
    __syncthreads();

    // ======================= pass 2: attn/anti AV ===========================
    // warp = rows [rq*16, rq*16+16) x dcols [kh*32, kh*32+32)
    int dh = kh;
    float iz0 = izt[rq * 16 + g];
    float iz1 = izt[rq * 16 + g + 8];

    float4 vreg[4];
    #pragma unroll
    for (int p = 0; p < 4; p++) {
        const float* src = (p < 2) ? Vcb : Vfb;
        int i4 = tid + (p & 1) * 256;
        vreg[p] = *(const float4*)&src[(i4 >> 4) * 64 + (i4 & 15) * 4];
    }

    float accA[4][4], accW[4][4];
    #pragma unroll
    for (int dp = 0; dp < 4; dp++)
        #pragma unroll
        for (int e = 0; e < 4; e++) { accA[dp][e] = 0.f; accW[dp][e] = 0.f; }
    float sw0 = 0.f, sw1 = 0.f;

    for (int t = 0; t < 64; t++) {
        uint32_t bb = TB + (t & 1) * TBSTRIDE;
        #pragma unroll
        for (int p = 0; p < 4; p++) {
            int arr = p >> 1;
            int i4 = tid + (p & 1) * 256;
            int key = i4 >> 4, bk = i4 & 15;
            *(float4*)&smu[bb + arr * 2048 + key * 64 + ((bk ^ (key & 7)) << 2)] = vreg[p];
        }
        __syncthreads();
        if (t < 63) {
            #pragma unroll
            for (int p = 0; p < 4; p++) {
                const float* src = (p < 2) ? Vcb : Vfb;
                int i4 = tid + (p & 1) * 256;
                vreg[p] = *(const float4*)&src[(t + 1) * 2048 + (i4 >> 4) * 64 + (i4 & 15) * 4];
            }
        }

        // p for this warp's 16 rows, all 32 keys (4 coalesced LDG.128)
        const float4* pg = &g_p[((blk * 4 + rq) * 64 + t) * 128 + lane];
        float4 p4[4];
        #pragma unroll
        for (int j = 0; j < 4; j++) p4[j] = pg[j * 32];

        #pragma unroll
        for (int j = 0; j < 4; j++) {
            float a0 = p4[j].x * iz0, a1 = p4[j].y * iz1;
            float a2 = p4[j].z * iz0, a3 = p4[j].w * iz1;
            float w0 = __expf(-a0), w1 = __expf(-a1), w2 = __expf(-a2), w3 = __expf(-a3);
            sw0 += w0 + w2; sw1 += w1 + w3;
            uint32_t A0 = f2tf(a0), A1 = f2tf(a1), A2 = f2tf(a2), A3 = f2tf(a3);
            uint32_t W0 = f2tf(w0), W1 = f2tf(w1), W2 = f2tf(w2), W3 = f2tf(w3);
            int rowc = j * 8 + c;
            #pragma unroll
            for (int dp = 0; dp < 4; dp++) {
                int dcol = (dh * 4 + dp) * 8 + g;
                int bk = dcol >> 2;
                uint32_t o0 = rowc * 64 + ((bk ^ c) << 2) + (dcol & 3);
                uint32_t o1 = (rowc + 4) * 64 + ((bk ^ (c + 4)) << 2) + (dcol & 3);
                uint32_t bc0 = smu[bb + o0];
                uint32_t bc1 = smu[bb + o1];
                uint32_t bf0 = smu[bb + 2048 + o0];
                uint32_t bf1 = smu[bb + 2048 + o1];
                mma_tf32(accA[dp], A0, A1, A2, A3, bc0, bc1);
                mma_tf32(accW[dp], W0, W1, W2, W3, bf0, bf1);
            }
        }
    }

    // anti row sums are warp-complete: quad-reduce + write out
    sw0 += __shfl_xor_sync(~0u, sw0, 1);
    sw0 += __shfl_xor_sync(~0u, sw0, 2);
    sw1 += __shfl_xor_sync(~0u, sw1, 1);
    sw1 += __shfl_xor_sync(~0u, sw1, 2);
    float iw0 = (1.f - spv) / sw0, iw1 = (1.f - spv) / sw1;

    int r = qt * 64 + rq * 16 + g;
    #pragma unroll
    for (int dp = 0; dp < 4; dp++) {
        int col = h * 64 + (dh * 4 + dp) * 8 + 2 * c;
        *(float2*)&ob[(n * T_ + r) * D_ + col] =
            make_float2(spv * accA[dp][0] + iw0 * accW[dp][0],
                        spv * accA[dp][1] + iw0 * accW[dp][1]);
        *(float2*)&ob[(n * T_ + r + 8) * D_ + col] =
            make_float2(spv * accA[dp][2] + iw1 * accW[dp][2],
                        spv * accA[dp][3] + iw1 * accW[dp][3]);
    }
}

// ---------------------------------------------------------------------------
extern "C" void kernel_launch(void* const* d_in, const int* in_sizes, int n_in,
                              void* d_out, int out_size) {
    const float* x   = (const float*)d_in[0];
    const float* y   = (const float*)d_in[1];
    const float* iw  = (const float*)d_in[2];
    const float* lw  = (const float*)d_in[3];
    const float* isc = (const float*)d_in[4];
    const float* lsc = (const float*)d_in[5];
    const float* sp  = (const float*)d_in[6];
    float* out = (float*)d_out;

    const int ATTN_SMEM = SMEM_WORDS * 4;   // 49664 bytes
    cudaFuncSetAttribute(attn_kernel, cudaFuncAttributeMaxDynamicSharedMemorySize, ATTN_SMEM);

    scale_kernel<<<1, 32>>>(isc, lsc);

    dim3 gq(1536 / 64, 4096 / 128, 2);
    qkv_tf32_kernel<<<gq, 256>>>(x, y, iw, lw);

    dim3 g2(T_ / 64, H_, 4);
    attn_kernel<<<g2, 256, ATTN_SMEM>>>(sp, out);
}

// round 14
// speedup vs baseline: 1.0170x; 1.0170x over previous
#include <cuda_runtime.h>
#include <cstdint>

#define N_  2
#define T_  2048
#define D_  512
#define H_  8
#define HD_ 64
#define NTD (N_*T_*D_)
#define NHTHD (N_*H_*T_*HD_)

// Scratch: [stream][q/k/v][n,h,t,hd], values pre-rounded to tf32 (rna)
__device__ float g_buf[2][3][NHTHD];
__device__ float g_sc[2][H_*HD_];
// p scratch: [blk(512)][warp(8)][t(64)][j(4)*32+lane] float4 (A-frag layout)
__device__ float4 g_p[512u*8u*64u*128u];

// attn smem word offsets
#define QP 0                    // Q A-frags: 64 groups * 132 = 8448 words (izt reuses words 0..191 after pass 1)
#define TB 8448                 // tile double-buffer
#define TBSTRIDE 4096
#define SMEM_WORDS (8448 + 2*4096)   // 16640 words = 66560 B

#define NWORK 512
#define PERSIST 296             // 148 SMs x 2 CTAs

// ---------------------------------------------------------------------------
__global__ void scale_kernel(const float* __restrict__ isc,
                             const float* __restrict__ lsc) {
    int i = threadIdx.x;
    if (i >= 16) return;
    int s = i >> 3, h = i & 7;
    const float* src = (s == 0 ? isc : lsc) + h * HD_;
    float m = -1e30f;
    for (int d = 0; d < HD_; d++) m = fmaxf(m, src[d]);
    float Z = 0.f;
    for (int d = 0; d < HD_; d++) Z += __expf(src[d] - m);
    float inv = 1.f / Z;
    for (int d = 0; d < HD_; d++) g_sc[s][h*HD_ + d] = __expf(src[d] - m) * inv;
}

__device__ __forceinline__ uint32_t f2tf(float x) {
    uint32_t r;
    asm("cvt.rna.tf32.f32 %0, %1;" : "=r"(r) : "f"(x));
    return r;
}
__device__ __forceinline__ float tf32r(float x) { return __uint_as_float(f2tf(x)); }

__device__ __forceinline__ void mma_tf32(float (&d)[4],
                                         uint32_t a0, uint32_t a1, uint32_t a2, uint32_t a3,
                                         uint32_t b0, uint32_t b1) {
    asm volatile(
        "mma.sync.aligned.m16n8k8.row.col.f32.tf32.tf32.f32 "
        "{%0,%1,%2,%3}, {%4,%5,%6,%7}, {%8,%9}, {%0,%1,%2,%3};"
        : "+f"(d[0]), "+f"(d[1]), "+f"(d[2]), "+f"(d[3])
        : "r"(a0), "r"(a1), "r"(a2), "r"(a3), "r"(b0), "r"(b1));
}

// ---------------------------------------------------------------------------
// QKV projection, tf32 mma, 128(M) x 64(N) tiles, K=512, reg-prefetched.
// Both streams in one launch (blockIdx.z). Writes tf32-rounded fp32.
// ---------------------------------------------------------------------------
__global__ __launch_bounds__(256, 2)
void qkv_tf32_kernel(const float* __restrict__ x, const float* __restrict__ y,
                     const float* __restrict__ iw, const float* __restrict__ lw) {
    __shared__ uint32_t ap[4224];
    __shared__ uint32_t bp[2112];
    int stream = blockIdx.z;
    const float* z = stream ? y : x;
    const float* W = stream ? lw : iw;
    int tid = threadIdx.x;
    int w = tid >> 5, lane = tid & 31;
    int g = lane >> 2, c = lane & 3;
    int rq = w & 3, nh = w >> 2;
    int c0 = blockIdx.x * 64;
    int m0 = blockIdx.y * 128;

    float acc[2][4][4];
    #pragma unroll
    for (int a = 0; a < 2; a++)
        #pragma unroll
        for (int b = 0; b < 4; b++)
            #pragma unroll
            for (int e = 0; e < 4; e++) acc[a][b][e] = 0.f;

    float4 zr[4], wr[2];
    #pragma unroll
    for (int p = 0; p < 4; p++) {
        int i4 = tid + p * 256;
        zr[p] = *(const float4*)&z[(m0 + (i4 >> 3)) * 512 + (i4 & 7) * 4];
    }
    #pragma unroll
    for (int p = 0; p < 2; p++) {
        int i4 = tid + p * 256;
        wr[p] = *(const float4*)&W[(c0 + (i4 >> 3)) * 512 + (i4 & 7) * 4];
    }

    for (int it = 0; it < 16; it++) {
        __syncthreads();
        #pragma unroll
        for (int p = 0; p < 4; p++) {
            int i4 = tid + p * 256;
            int row = i4 >> 3, kq = i4 & 7;
            int base = ((row >> 4) * 4 + (kq >> 1)) * 132 + (row & 7) * 16
                     + (kq & 1) * 2 + ((row >> 3) & 1);
            ap[base + 0]  = f2tf(zr[p].x);
            ap[base + 4]  = f2tf(zr[p].y);
            ap[base + 8]  = f2tf(zr[p].z);
            ap[base + 12] = f2tf(zr[p].w);
        }
        #pragma unroll
        for (int p = 0; p < 2; p++) {
            int i4 = tid + p * 256;
            int col = i4 >> 3, kq = i4 & 7;
            int base = ((col >> 3) * 4 + (kq >> 1)) * 66 + (col & 7) * 8 + (kq & 1);
            bp[base + 0] = f2tf(wr[p].x);
            bp[base + 2] = f2tf(wr[p].y);
            bp[base + 4] = f2tf(wr[p].z);
            bp[base + 6] = f2tf(wr[p].w);
        }
        __syncthreads();
        if (it < 15) {
            int k0 = (it + 1) * 32;
            #pragma unroll
            for (int p = 0; p < 4; p++) {
                int i4 = tid + p * 256;
                zr[p] = *(const float4*)&z[(m0 + (i4 >> 3)) * 512 + k0 + (i4 & 7) * 4];
            }
            #pragma unroll
            for (int p = 0; p < 2; p++) {
                int i4 = tid + p * 256;
                wr[p] = *(const float4*)&W[(c0 + (i4 >> 3)) * 512 + k0 + (i4 & 7) * 4];
            }
        }
        #pragma unroll
        for (int ks = 0; ks < 4; ks++) {
            uint4 a0 = *(const uint4*)&ap[((rq * 2 + 0) * 4 + ks) * 132 + lane * 4];
            uint4 a1 = *(const uint4*)&ap[((rq * 2 + 1) * 4 + ks) * 132 + lane * 4];
            #pragma unroll
            for (int np = 0; np < 4; np++) {
                uint2 b = *(const uint2*)&bp[((nh * 4 + np) * 4 + ks) * 66 + lane * 2];
                mma_tf32(acc[0][np], a0.x, a0.y, a0.z, a0.w, b.x, b.y);
                mma_tf32(acc[1][np], a1.x, a1.y, a1.z, a1.w, b.x, b.y);
            }
        }
    }

    int three = c0 >> 9;
    int h = (c0 >> 6) & 7;
    float* dst = g_buf[stream][three];
    #pragma unroll
    for (int grp = 0; grp < 2; grp++) {
        #pragma unroll
        for (int np = 0; np < 4; np++) {
            int colb = nh * 32 + np * 8 + 2 * c;
            float sx = 1.f, sy = 1.f;
            if (three == 0) {
                float2 s2 = *(const float2*)&g_sc[stream][h * 64 + colb];
                sx = s2.x; sy = s2.y;
            }
            int m = m0 + rq * 32 + grp * 16 + g;
            int nn = m >> 11, t = m & 2047;
            *(float2*)&dst[((nn * 8 + h) * 2048 + t) * 64 + colb] =
                make_float2(tf32r(acc[grp][np][0] * sx), tf32r(acc[grp][np][1] * sy));
            int m2 = m + 8;
            int nn2 = m2 >> 11, t2 = m2 & 2047;
            *(float2*)&dst[((nn2 * 8 + h) * 2048 + t2) * 64 + colb] =
                make_float2(tf32r(acc[grp][np][2] * sx), tf32r(acc[grp][np][3] * sy));
        }
    }
}

// ---------------------------------------------------------------------------
// Dual attention, persistent blocks. Work item = (stream, n, h, 128-row
// q-tile); 296 CTAs loop over 512 items. Per item (identical to R11):
// Pass 1 (16 rows/warp, Q frags in regs): QK^T, Z = sum exp(S),
//         p = exp(S) -> A-frag layout -> coalesced STG to g_p; iZ table.
// Pass 2 (32 rows x 32 dcols/warp): a = p*iZ, w = exp(-a); AV mmas with
//         V B-frags hoisted across the two row-groups.
// anti = softmax(max(attn)-attn) == softmax(-attn)
// ---------------------------------------------------------------------------
__global__ __launch_bounds__(256, 2)
void attn_kernel(const float* __restrict__ sp, float* __restrict__ out) {
    extern __shared__ uint32_t smu[];
    int tid = threadIdx.x;
    int w = tid >> 5, lane = tid & 31;
    int g = lane >> 2, c = lane & 3;
    float spv = *sp;
    int srcA = (lane & ~3) | (c >> 1);
    int srcB = srcA + 2;
    bool odd = lane & 1;

    for (int work = blockIdx.x; work < NWORK; work += gridDim.x) {
        // 512 items = 16 q-tiles x 8 heads x 4 (stream,n)
        int qt = work & 15, h = (work >> 4) & 7, zb = work >> 7;
        int s = zb >> 1, n = zb & 1;
        int blk = work;

        const float* Qb  = g_buf[s][0]     + ((n * H_ + h) * T_ + qt * 128) * HD_;
        const float* Kb  = g_buf[1 - s][1] + ((n * H_ + h) * T_) * HD_;
        const float* Vcb = g_buf[1 - s][2] + ((n * H_ + h) * T_) * HD_;
        const float* Vfb = g_buf[s][2]     + ((n * H_ + h) * T_) * HD_;
        float* ob = out + s * NTD;

        // stage Q [128x64] into A-frag layout (values pre-rounded)
        #pragma unroll
        for (int p = 0; p < 8; p++) {
            int i4 = tid + p * 256;
            int row = i4 >> 4, kq = i4 & 15;
            float4 qv = *(const float4*)&Qb[row * 64 + kq * 4];
            int base = QP + ((row >> 4) * 8 + (kq >> 1)) * 132 + (row & 7) * 16
                     + (kq & 1) * 2 + ((row >> 3) & 1);
            smu[base + 0]  = __float_as_uint(qv.x);
            smu[base + 4]  = __float_as_uint(qv.y);
            smu[base + 8]  = __float_as_uint(qv.z);
            smu[base + 12] = __float_as_uint(qv.w);
        }
        __syncthreads();

        // this warp's Q A-frags in registers for pass 1
        uint4 qf[8];
        #pragma unroll
        for (int ks = 0; ks < 8; ks++)
            qf[ks] = *(const uint4*)&smu[QP + (w * 8 + ks) * 132 + lane * 4];

        // ================= pass 1: Z = sum exp(S), p -> gmem ================
        float4 kreg[2];
        #pragma unroll
        for (int p = 0; p < 2; p++) {
            int i4 = tid + p * 256;
            kreg[p] = *(const float4*)&Kb[(i4 >> 4) * 64 + (i4 & 15) * 4];
        }

        float zs0 = 0.f, zs1 = 0.f;
        for (int t = 0; t < 64; t++) {
            uint32_t kb = TB + (t & 1) * TBSTRIDE;
            #pragma unroll
            for (int p = 0; p < 2; p++) {
                int i4 = tid + p * 256;
                int key = i4 >> 4, bk = i4 & 15;
                *(float4*)&smu[kb + key * 64 + ((bk ^ (key & 7)) << 2)] = kreg[p];
            }
            __syncthreads();
            if (t < 63) {
                #pragma unroll
                for (int p = 0; p < 2; p++) {
                    int i4 = tid + p * 256;
                    kreg[p] = *(const float4*)&Kb[(t + 1) * 2048 + (i4 >> 4) * 64 + (i4 & 15) * 4];
                }
            }
            float S[4][4];
            #pragma unroll
            for (int j = 0; j < 4; j++) { S[j][0]=0.f; S[j][1]=0.f; S[j][2]=0.f; S[j][3]=0.f; }
            #pragma unroll
            for (int ks = 0; ks < 8; ks++) {
                uint4 a = qf[ks];
                #pragma unroll
                for (int j = 0; j < 4; j++) {
                    uint32_t base = kb + (j * 8 + g) * 64 + c;
                    uint32_t b0 = smu[base + (((ks * 2) ^ g) << 2)];
                    uint32_t b1 = smu[base + (((ks * 2 + 1) ^ g) << 2)];
                    mma_tf32(S[j], a.x, a.y, a.z, a.w, b0, b1);
                }
            }
            float4* pg = &g_p[((blk * 8 + w) * 64 + t) * 128 + lane];
            #pragma unroll
            for (int j = 0; j < 4; j++) {
                float p0 = __expf(S[j][0]);
                float p1 = __expf(S[j][1]);
                float p2 = __expf(S[j][2]);
                float p3 = __expf(S[j][3]);
                zs0 += p0 + p1;
                zs1 += p2 + p3;
                float x0 = __shfl_sync(~0u, p0, srcA);
                float x1 = __shfl_sync(~0u, p1, srcA);
                float y0 = __shfl_sync(~0u, p2, srcA);
                float y1 = __shfl_sync(~0u, p3, srcA);
                float u0 = __shfl_sync(~0u, p0, srcB);
                float u1 = __shfl_sync(~0u, p1, srcB);
                float v0 = __shfl_sync(~0u, p2, srcB);
                float v1 = __shfl_sync(~0u, p3, srcB);
                float4 o;
                o.x = odd ? x1 : x0;
                o.y = odd ? y1 : y0;
                o.z = odd ? u1 : u0;
                o.w = odd ? v1 : v0;
                pg[j * 32] = o;
            }
        }
        zs0 += __shfl_xor_sync(~0u, zs0, 1);
        zs0 += __shfl_xor_sync(~0u, zs0, 2);
        zs1 += __shfl_xor_sync(~0u, zs1, 1);
        zs1 += __shfl_xor_sync(~0u, zs1, 2);

        // publish iZ per row (QP words 0..127 are dead until next work item)
        float* izt = (float*)smu;
        __syncthreads();   // all reads of QP(Q frags) done (qf in regs; pass1 finished)
        if (c == 0) {
            izt[w * 16 + g]     = 1.f / zs0;
            izt[w * 16 + g + 8] = 1.f / zs1;
        }
        __syncthreads();

        // ===================== pass 2: attn/anti AV =========================
        int rq = w & 3, dh = w >> 2;
        float iz0[2], iz1[2];
        #pragma unroll
        for (int grp = 0; grp < 2; grp++) {
            int rgi = rq * 2 + grp;
            iz0[grp] = izt[rgi * 16 + g];
            iz1[grp] = izt[rgi * 16 + g + 8];
        }

        float4 vreg[4];
        #pragma unroll
        for (int p = 0; p < 4; p++) {
            const float* src = (p < 2) ? Vcb : Vfb;
            int i4 = tid + (p & 1) * 256;
            vreg[p] = *(const float4*)&src[(i4 >> 4) * 64 + (i4 & 15) * 4];
        }

        float accA[2][4][4], accW[2][4][4];
        #pragma unroll
        for (int grp = 0; grp < 2; grp++)
            #pragma unroll
            for (int dp = 0; dp < 4; dp++)
                #pragma unroll
                for (int e = 0; e < 4; e++) { accA[grp][dp][e] = 0.f; accW[grp][dp][e] = 0.f; }
        float sw0[2] = {0.f, 0.f}, sw1[2] = {0.f, 0.f};

        for (int t = 0; t < 64; t++) {
            uint32_t bb = TB + (t & 1) * TBSTRIDE;
            #pragma unroll
            for (int p = 0; p < 4; p++) {
                int arr = p >> 1;
                int i4 = tid + (p & 1) * 256;
                int key = i4 >> 4, bk = i4 & 15;
                *(float4*)&smu[bb + arr * 2048 + key * 64 + ((bk ^ (key & 7)) << 2)] = vreg[p];
            }
            __syncthreads();
            if (t < 63) {
                #pragma unroll
                for (int p = 0; p < 4; p++) {
                    const float* src = (p < 2) ? Vcb : Vfb;
                    int i4 = tid + (p & 1) * 256;
                    vreg[p] = *(const float4*)&src[(t + 1) * 2048 + (i4 >> 4) * 64 + (i4 & 15) * 4];
                }
            }

            float4 p4[2][4];
            #pragma unroll
            for (int grp = 0; grp < 2; grp++) {
                const float4* pg = &g_p[((blk * 8 + rq * 2 + grp) * 64 + t) * 128 + lane];
                #pragma unroll
                for (int j = 0; j < 4; j++) p4[grp][j] = pg[j * 32];
            }

            #pragma unroll
            for (int j = 0; j < 4; j++) {
                uint32_t Af[2][4], Wf[2][4];
                #pragma unroll
                for (int grp = 0; grp < 2; grp++) {
                    float a0 = p4[grp][j].x * iz0[grp], a1 = p4[grp][j].y * iz1[grp];
                    float a2 = p4[grp][j].z * iz0[grp], a3 = p4[grp][j].w * iz1[grp];
                    float w0 = __expf(-a0), w1 = __expf(-a1), w2 = __expf(-a2), w3 = __expf(-a3);
                    sw0[grp] += w0 + w2; sw1[grp] += w1 + w3;
                    Af[grp][0] = f2tf(a0); Af[grp][1] = f2tf(a1);
                    Af[grp][2] = f2tf(a2); Af[grp][3] = f2tf(a3);
                    Wf[grp][0] = f2tf(w0); Wf[grp][1] = f2tf(w1);
                    Wf[grp][2] = f2tf(w2); Wf[grp][3] = f2tf(w3);
                }
                int rowc = j * 8 + c;
                #pragma unroll
                for (int dp = 0; dp < 4; dp++) {
                    int dcol = (dh * 4 + dp) * 8 + g;
                    int bk = dcol >> 2;
                    uint32_t o0 = rowc * 64 + ((bk ^ c) << 2) + (dcol & 3);
                    uint32_t o1 = (rowc + 4) * 64 + ((bk ^ (c + 4)) << 2) + (dcol & 3);
                    uint32_t bc0 = smu[bb + o0];
                    uint32_t bc1 = smu[bb + o1];
                    uint32_t bf0 = smu[bb + 2048 + o0];
                    uint32_t bf1 = smu[bb + 2048 + o1];
                    #pragma unroll
                    for (int grp = 0; grp < 2; grp++) {
                        mma_tf32(accA[grp][dp], Af[grp][0], Af[grp][1], Af[grp][2], Af[grp][3], bc0, bc1);
                        mma_tf32(accW[grp][dp], Wf[grp][0], Wf[grp][1], Wf[grp][2], Wf[grp][3], bf0, bf1);
                    }
                }
            }
        }

        // anti row sums (warp-complete): quad-reduce + write out
        #pragma unroll
        for (int grp = 0; grp < 2; grp++) {
            float s0 = sw0[grp], s1 = sw1[grp];
            s0 += __shfl_xor_sync(~0u, s0, 1);
            s0 += __shfl_xor_sync(~0u, s0, 2);
            s1 += __shfl_xor_sync(~0u, s1, 1);
            s1 += __shfl_xor_sync(~0u, s1, 2);
            float iw0 = (1.f - spv) / s0, iw1 = (1.f - spv) / s1;
            int r = qt * 128 + rq * 32 + grp * 16 + g;
            #pragma unroll
            for (int dp = 0; dp < 4; dp++) {
                int col = h * 64 + (dh * 4 + dp) * 8 + 2 * c;
                *(float2*)&ob[(n * T_ + r) * D_ + col] =
                    make_float2(spv * accA[grp][dp][0] + iw0 * accW[grp][dp][0],
                                spv * accA[grp][dp][1] + iw0 * accW[grp][dp][1]);
                *(float2*)&ob[(n * T_ + r + 8) * D_ + col] =
                    make_float2(spv * accA[grp][dp][2] + iw1 * accW[grp][dp][2],
                                spv * accA[grp][dp][3] + iw1 * accW[grp][dp][3]);
            }
        }
        __syncthreads();   // item done before next item's Q staging
    }
}

// ---------------------------------------------------------------------------
extern "C" void kernel_launch(void* const* d_in, const int* in_sizes, int n_in,
                              void* d_out, int out_size) {
    const float* x   = (const float*)d_in[0];
    const float* y   = (const float*)d_in[1];
    const float* iw  = (const float*)d_in[2];
    const float* lw  = (const float*)d_in[3];
    const float* isc = (const float*)d_in[4];
    const float* lsc = (const float*)d_in[5];
    const float* sp  = (const float*)d_in[6];
    float* out = (float*)d_out;

    const int ATTN_SMEM = SMEM_WORDS * 4;   // 66560 bytes
    cudaFuncSetAttribute(attn_kernel, cudaFuncAttributeMaxDynamicSharedMemorySize, ATTN_SMEM);

    scale_kernel<<<1, 32>>>(isc, lsc);

    dim3 gq(1536 / 64, 4096 / 128, 2);
    qkv_tf32_kernel<<<gq, 256>>>(x, y, iw, lw);

    attn_kernel<<<PERSIST, 256, ATTN_SMEM>>>(sp, out);
}

// round 16
// speedup vs baseline: 1.3996x; 1.3762x over previous
#include <cuda_runtime.h>
#include <cuda_fp16.h>
#include <cstdint>

#define N_  2
#define T_  2048
#define D_  512
#define H_  8
#define HD_ 64
#define NTD (N_*T_*D_)
#define NHTHD (N_*H_*T_*HD_)

// Scratch: [stream][q/k/v][n,h,t,hd]; Q/K tf32-rounded, V raw fp32
__device__ float g_buf[2][3][NHTHD];
__device__ float g_sc[2][H_*HD_];
// Sum over keys of V per (stream*2+n)*8+h, per dim
__device__ float g_sv[32][64];
// p scratch (fp16x2 pairs): [blk(512)][warp(8)][t(64)][j(4)*32+lane] uint2
__device__ uint2 g_p[512u*8u*64u*128u];

// attn smem word offsets
#define QP 0                    // Q A-frags: 64 groups * 132 = 8448 words (izt reuses 0..127 after pass 1)
#define TB 8448                 // tile double-buffer, 2048 words per buf
                                // pass1: K (2048 fp32 words); pass2: Vc f16x2 @+0 (1024), Vf @+1024
#define TBSTRIDE 2048
#define SMEM_WORDS (8448 + 2*2048)   // 12544 words = 50176 B

// ---------------------------------------------------------------------------
__global__ void scale_kernel(const float* __restrict__ isc,
                             const float* __restrict__ lsc) {
    int i = threadIdx.x;
    if (i >= 16) return;
    int s = i >> 3, h = i & 7;
    const float* src = (s == 0 ? isc : lsc) + h * HD_;
    float m = -1e30f;
    for (int d = 0; d < HD_; d++) m = fmaxf(m, src[d]);
    float Z = 0.f;
    for (int d = 0; d < HD_; d++) Z += __expf(src[d] - m);
    float inv = 1.f / Z;
    for (int d = 0; d < HD_; d++) g_sc[s][h*HD_ + d] = __expf(src[d] - m) * inv;
}

// Sum of V over keys: one block per (stream,n,h)
__global__ void sumv_kernel() {
    __shared__ float sm[256];
    int sb = blockIdx.x;
    int s = sb >> 4, n = (sb >> 3) & 1, h = sb & 7;
    const float* V = g_buf[s][2] + ((n * H_ + h) * T_) * HD_;
    int tid = threadIdx.x;
    int d = tid & 63, tc = tid >> 6;
    float sum = 0.f;
    for (int t = tc; t < T_; t += 4) sum += V[t * 64 + d];
    sm[tid] = sum;
    __syncthreads();
    if (tid < 64)
        g_sv[sb][tid] = sm[tid] + sm[tid + 64] + sm[tid + 128] + sm[tid + 192];
}

__device__ __forceinline__ uint32_t f2tf(float x) {
    uint32_t r;
    asm("cvt.rna.tf32.f32 %0, %1;" : "=r"(r) : "f"(x));
    return r;
}
__device__ __forceinline__ float tf32r(float x) { return __uint_as_float(f2tf(x)); }

__device__ __forceinline__ uint32_t packh2(float even, float odd) {
    __half2 h = __floats2half2_rn(even, odd);   // .x (low) = even
    return *(uint32_t*)&h;
}
__device__ __forceinline__ float2 unpackh2(uint32_t u) {
    __half2 h = *(__half2*)&u;
    return __half22float2(h);                   // .x = low = even
}

__device__ __forceinline__ void mma_tf32(float (&d)[4],
                                         uint32_t a0, uint32_t a1, uint32_t a2, uint32_t a3,
                                         uint32_t b0, uint32_t b1) {
    asm volatile(
        "mma.sync.aligned.m16n8k8.row.col.f32.tf32.tf32.f32 "
        "{%0,%1,%2,%3}, {%4,%5,%6,%7}, {%8,%9}, {%0,%1,%2,%3};"
        : "+f"(d[0]), "+f"(d[1]), "+f"(d[2]), "+f"(d[3])
        : "r"(a0), "r"(a1), "r"(a2), "r"(a3), "r"(b0), "r"(b1));
}

__device__ __forceinline__ void mma_f16(float (&d)[4],
                                        uint32_t a0, uint32_t a1, uint32_t a2, uint32_t a3,
                                        uint32_t b0, uint32_t b1) {
    asm volatile(
        "mma.sync.aligned.m16n8k16.row.col.f32.f16.f16.f32 "
        "{%0,%1,%2,%3}, {%4,%5,%6,%7}, {%8,%9}, {%0,%1,%2,%3};"
        : "+f"(d[0]), "+f"(d[1]), "+f"(d[2]), "+f"(d[3])
        : "r"(a0), "r"(a1), "r"(a2), "r"(a3), "r"(b0), "r"(b1));
}

// ---------------------------------------------------------------------------
// QKV projection, tf32 mma, 128(M) x 64(N) tiles, K=512, reg-prefetched.
// Both streams in one launch (blockIdx.z). Q/K tf32-rounded, V raw fp32.
// ---------------------------------------------------------------------------
__global__ __launch_bounds__(256, 2)
void qkv_tf32_kernel(const float* __restrict__ x, const float* __restrict__ y,
                     const float* __restrict__ iw, const float* __restrict__ lw) {
    __shared__ uint32_t ap[4224];
    __shared__ uint32_t bp[2112];
    int stream = blockIdx.z;
    const float* z = stream ? y : x;
    const float* W = stream ? lw : iw;
    int tid = threadIdx.x;
    int w = tid >> 5, lane = tid & 31;
    int g = lane >> 2, c = lane & 3;
    int rq = w & 3, nh = w >> 2;
    int c0 = blockIdx.x * 64;
    int m0 = blockIdx.y * 128;

    float acc[2][4][4];
    #pragma unroll
    for (int a = 0; a < 2; a++)
        #pragma unroll
        for (int b = 0; b < 4; b++)
            #pragma unroll
            for (int e = 0; e < 4; e++) acc[a][b][e] = 0.f;

    float4 zr[4], wr[2];
    #pragma unroll
    for (int p = 0; p < 4; p++) {
        int i4 = tid + p * 256;
        zr[p] = *(const float4*)&z[(m0 + (i4 >> 3)) * 512 + (i4 & 7) * 4];
    }
    #pragma unroll
    for (int p = 0; p < 2; p++) {
        int i4 = tid + p * 256;
        wr[p] = *(const float4*)&W[(c0 + (i4 >> 3)) * 512 + (i4 & 7) * 4];
    }

    for (int it = 0; it < 16; it++) {
        __syncthreads();
        #pragma unroll
        for (int p = 0; p < 4; p++) {
            int i4 = tid + p * 256;
            int row = i4 >> 3, kq = i4 & 7;
            int base = ((row >> 4) * 4 + (kq >> 1)) * 132 + (row & 7) * 16
                     + (kq & 1) * 2 + ((row >> 3) & 1);
            ap[base + 0]  = f2tf(zr[p].x);
            ap[base + 4]  = f2tf(zr[p].y);
            ap[base + 8]  = f2tf(zr[p].z);
            ap[base + 12] = f2tf(zr[p].w);
        }
        #pragma unroll
        for (int p = 0; p < 2; p++) {
            int i4 = tid + p * 256;
            int col = i4 >> 3, kq = i4 & 7;
            int base = ((col >> 3) * 4 + (kq >> 1)) * 66 + (col & 7) * 8 + (kq & 1);
            bp[base + 0] = f2tf(wr[p].x);
            bp[base + 2] = f2tf(wr[p].y);
            bp[base + 4] = f2tf(wr[p].z);
            bp[base + 6] = f2tf(wr[p].w);
        }
        __syncthreads();
        if (it < 15) {
            int k0 = (it + 1) * 32;
            #pragma unroll
            for (int p = 0; p < 4; p++) {
                int i4 = tid + p * 256;
                zr[p] = *(const float4*)&z[(m0 + (i4 >> 3)) * 512 + k0 + (i4 & 7) * 4];
            }
            #pragma unroll
            for (int p = 0; p < 2; p++) {
                int i4 = tid + p * 256;
                wr[p] = *(const float4*)&W[(c0 + (i4 >> 3)) * 512 + k0 + (i4 & 7) * 4];
            }
        }
        #pragma unroll
        for (int ks = 0; ks < 4; ks++) {
            uint4 a0 = *(const uint4*)&ap[((rq * 2 + 0) * 4 + ks) * 132 + lane * 4];
            uint4 a1 = *(const uint4*)&ap[((rq * 2 + 1) * 4 + ks) * 132 + lane * 4];
            #pragma unroll
            for (int np = 0; np < 4; np++) {
                uint2 b = *(const uint2*)&bp[((nh * 4 + np) * 4 + ks) * 66 + lane * 2];
                mma_tf32(acc[0][np], a0.x, a0.y, a0.z, a0.w, b.x, b.y);
                mma_tf32(acc[1][np], a1.x, a1.y, a1.z, a1.w, b.x, b.y);
            }
        }
    }

    int three = c0 >> 9;
    int h = (c0 >> 6) & 7;
    float* dst = g_buf[stream][three];
    bool rnd = (three != 2);   // V stays raw fp32
    #pragma unroll
    for (int grp = 0; grp < 2; grp++) {
        #pragma unroll
        for (int np = 0; np < 4; np++) {
            int colb = nh * 32 + np * 8 + 2 * c;
            float sx = 1.f, sy = 1.f;
            if (three == 0) {
                float2 s2 = *(const float2*)&g_sc[stream][h * 64 + colb];
                sx = s2.x; sy = s2.y;
            }
            float v0 = acc[grp][np][0] * sx, v1 = acc[grp][np][1] * sy;
            float v2 = acc[grp][np][2] * sx, v3 = acc[grp][np][3] * sy;
            if (rnd) { v0 = tf32r(v0); v1 = tf32r(v1); v2 = tf32r(v2); v3 = tf32r(v3); }
            int m = m0 + rq * 32 + grp * 16 + g;
            int nn = m >> 11, t = m & 2047;
            *(float2*)&dst[((nn * 8 + h) * 2048 + t) * 64 + colb] = make_float2(v0, v1);
            int m2 = m + 8;
            int nn2 = m2 >> 11, t2 = m2 & 2047;
            *(float2*)&dst[((nn2 * 8 + h) * 2048 + t2) * 64 + colb] = make_float2(v2, v3);
        }
    }
}

// ---------------------------------------------------------------------------
// Dual attention. Block = (stream, n, h, 128-row q-tile), 8 warps x 16 rows.
// No-max softmax (|S| <= ~1).
// Pass 1 (16 rows/warp, Q frags in regs): QK^T tf32, Z = sum exp(S),
//         p = exp(S) packed f16x2 (identity C->A frag mapping) -> g_p.
// Pass 2 (32 rows x 32 dcols/warp): fp16 m16n8k16 AV mmas; anti uses
//         wm1 = expf(-a)-1 with SumV correction (fp16-safe).
// anti = softmax(max(attn)-attn) == softmax(-attn)
// ---------------------------------------------------------------------------
__global__ __launch_bounds__(256, 2)
void attn_kernel(const float* __restrict__ sp, float* __restrict__ out) {
    extern __shared__ uint32_t smu[];
    int tid = threadIdx.x;
    int w = tid >> 5, lane = tid & 31;
    int g = lane >> 2, c = lane & 3;
    int qt = blockIdx.x, h = blockIdx.y, zb = blockIdx.z;
    int s = zb >> 1, n = zb & 1;
    int blk = (zb * 8 + h) * 16 + qt;

    const float* Qb  = g_buf[s][0]     + ((n * H_ + h) * T_ + qt * 128) * HD_;
    const float* Kb  = g_buf[1 - s][1] + ((n * H_ + h) * T_) * HD_;
    const float* Vcb = g_buf[1 - s][2] + ((n * H_ + h) * T_) * HD_;
    const float* Vfb = g_buf[s][2]     + ((n * H_ + h) * T_) * HD_;
    float* ob = out + s * NTD;
    float spv = *sp;

    // stage Q [128x64] into A-frag layout once (values pre-rounded)
    #pragma unroll
    for (int p = 0; p < 8; p++) {
        int i4 = tid + p * 256;
        int row = i4 >> 4, kq = i4 & 15;
        float4 qv = *(const float4*)&Qb[row * 64 + kq * 4];
        int base = QP + ((row >> 4) * 8 + (kq >> 1)) * 132 + (row & 7) * 16
                 + (kq & 1) * 2 + ((row >> 3) & 1);
        smu[base + 0]  = __float_as_uint(qv.x);
        smu[base + 4]  = __float_as_uint(qv.y);
        smu[base + 8]  = __float_as_uint(qv.z);
        smu[base + 12] = __float_as_uint(qv.w);
    }
    __syncthreads();

    // pull this warp's Q A-frags into registers for the whole of pass 1
    uint4 qf[8];
    #pragma unroll
    for (int ks = 0; ks < 8; ks++)
        qf[ks] = *(const uint4*)&smu[QP + (w * 8 + ks) * 132 + lane * 4];

    // ================= pass 1: Z = sum exp(S), p -> gmem ====================
    float4 kreg[2];
    #pragma unroll
    for (int p = 0; p < 2; p++) {
        int i4 = tid + p * 256;
        kreg[p] = *(const float4*)&Kb[(i4 >> 4) * 64 + (i4 & 15) * 4];
    }

    float zs0 = 0.f, zs1 = 0.f;
    for (int t = 0; t < 64; t++) {
        uint32_t kb = TB + (t & 1) * TBSTRIDE;
        #pragma unroll
        for (int p = 0; p < 2; p++) {
            int i4 = tid + p * 256;
            int key = i4 >> 4, bk = i4 & 15;
            *(float4*)&smu[kb + key * 64 + ((bk ^ (key & 7)) << 2)] = kreg[p];
        }
        __syncthreads();
        if (t < 63) {
            #pragma unroll
            for (int p = 0; p < 2; p++) {
                int i4 = tid + p * 256;
                kreg[p] = *(const float4*)&Kb[(t + 1) * 2048 + (i4 >> 4) * 64 + (i4 & 15) * 4];
            }
        }
        float S[4][4];
        #pragma unroll
        for (int j = 0; j < 4; j++) { S[j][0]=0.f; S[j][1]=0.f; S[j][2]=0.f; S[j][3]=0.f; }
        #pragma unroll
        for (int ks = 0; ks < 8; ks++) {
            uint4 a = qf[ks];
            #pragma unroll
            for (int j = 0; j < 4; j++) {
                uint32_t base = kb + (j * 8 + g) * 64 + c;
                uint32_t b0 = smu[base + (((ks * 2) ^ g) << 2)];
                uint32_t b1 = smu[base + (((ks * 2 + 1) ^ g) << 2)];
                mma_tf32(S[j], a.x, a.y, a.z, a.w, b0, b1);
            }
        }
        // p = exp(S); Z accumulation; pack f16x2 (identity mapping, no shfl)
        uint2* pg = &g_p[(((unsigned)blk * 8 + w) * 64 + t) * 128 + lane];
        #pragma unroll
        for (int j = 0; j < 4; j++) {
            float p0 = __expf(S[j][0]);   // row g,   key even
            float p1 = __expf(S[j][1]);   // row g,   key odd
            float p2 = __expf(S[j][2]);   // row g+8, key even
            float p3 = __expf(S[j][3]);   // row g+8, key odd
            zs0 += p0 + p1;
            zs1 += p2 + p3;
            pg[j * 32] = make_uint2(packh2(p0, p1), packh2(p2, p3));
        }
    }
    zs0 += __shfl_xor_sync(~0u, zs0, 1);
    zs0 += __shfl_xor_sync(~0u, zs0, 2);
    zs1 += __shfl_xor_sync(~0u, zs1, 1);
    zs1 += __shfl_xor_sync(~0u, zs1, 2);

    // publish iZ per row (QP words 0..127 are dead now)
    float* izt = (float*)smu;
    __syncthreads();
    if (c == 0) {
        izt[w * 16 + g]     = 1.f / zs0;
        izt[w * 16 + g + 8] = 1.f / zs1;
    }
    __syncthreads();

    // ======================= pass 2: attn/anti AV ===========================
    // warp = rows [rq*32, rq*32+32) x dcols [dh*32, dh*32+32)
    int rq = w & 3, dh = w >> 2;
    float iz0[2], iz1[2];
    #pragma unroll
    for (int grp = 0; grp < 2; grp++) {
        int rgi = rq * 2 + grp;
        iz0[grp] = izt[rgi * 16 + g];
        iz1[grp] = izt[rgi * 16 + g + 8];
    }

    // V prefetch: [arr][wi][key01] = float2 over d-pair
    // idx = tid + wi*256: kp = idx>>5 (0..15), dm = (idx&31)*2
    float2 va[2][2][2];
    #pragma unroll
    for (int arr = 0; arr < 2; arr++) {
        const float* src = arr ? Vfb : Vcb;
        #pragma unroll
        for (int wi = 0; wi < 2; wi++) {
            int idx = tid + wi * 256;
            int kp = idx >> 5, dm = (idx & 31) * 2;
            va[arr][wi][0] = *(const float2*)&src[(2 * kp) * 64 + dm];
            va[arr][wi][1] = *(const float2*)&src[(2 * kp + 1) * 64 + dm];
        }
    }

    float accA[2][4][4], accW[2][4][4];
    #pragma unroll
    for (int grp = 0; grp < 2; grp++)
        #pragma unroll
        for (int dp = 0; dp < 4; dp++)
            #pragma unroll
            for (int e = 0; e < 4; e++) { accA[grp][dp][e] = 0.f; accW[grp][dp][e] = 0.f; }
    float sw0[2] = {0.f, 0.f}, sw1[2] = {0.f, 0.f};

    for (int t = 0; t < 64; t++) {
        uint32_t bb = TB + (t & 1) * TBSTRIDE;
        #pragma unroll
        for (int arr = 0; arr < 2; arr++)
            #pragma unroll
            for (int wi = 0; wi < 2; wi++) {
                int idx = tid + wi * 256;
                int kp = idx >> 5, dm = (idx & 31) * 2;
                uint32_t wb = bb + arr * 1024 + kp * 64 + (dm ^ ((kp & 3) << 3));
                *(uint2*)&smu[wb] = make_uint2(
                    packh2(va[arr][wi][0].x, va[arr][wi][1].x),
                    packh2(va[arr][wi][0].y, va[arr][wi][1].y));
            }
        __syncthreads();
        if (t < 63) {
            #pragma unroll
            for (int arr = 0; arr < 2; arr++) {
                const float* src = (arr ? Vfb : Vcb) + (t + 1) * 2048;
                #pragma unroll
                for (int wi = 0; wi < 2; wi++) {
                    int idx = tid + wi * 256;
                    int kp = idx >> 5, dm = (idx & 31) * 2;
                    va[arr][wi][0] = *(const float2*)&src[(2 * kp) * 64 + dm];
                    va[arr][wi][1] = *(const float2*)&src[(2 * kp + 1) * 64 + dm];
                }
            }
        }

        #pragma unroll
        for (int J = 0; J < 2; J++) {
            // build fp16 A-frags for both row-groups from p (j = 2J, 2J+1)
            uint32_t Aa[2][2][2], Ww[2][2][2];   // [grp][jj][row01]
            #pragma unroll
            for (int grp = 0; grp < 2; grp++) {
                const uint2* pg = &g_p[(((unsigned)blk * 8 + rq * 2 + grp) * 64 + t) * 128 + lane];
                #pragma unroll
                for (int jj = 0; jj < 2; jj++) {
                    uint2 u = pg[(2 * J + jj) * 32];
                    float2 f0 = unpackh2(u.x);   // row g:   (even, odd)
                    float2 f1 = unpackh2(u.y);   // row g+8: (even, odd)
                    float a0 = f0.x * iz0[grp], a1 = f0.y * iz0[grp];
                    float a2 = f1.x * iz1[grp], a3 = f1.y * iz1[grp];
                    float m0 = __expf(-a0) - 1.f, m1 = __expf(-a1) - 1.f;
                    float m2 = __expf(-a2) - 1.f, m3 = __expf(-a3) - 1.f;
                    sw0[grp] += m0 + m1;
                    sw1[grp] += m2 + m3;
                    Aa[grp][jj][0] = packh2(a0, a1);
                    Aa[grp][jj][1] = packh2(a2, a3);
                    Ww[grp][jj][0] = packh2(m0, m1);
                    Ww[grp][jj][1] = packh2(m2, m3);
                }
            }
            #pragma unroll
            for (int dp = 0; dp < 4; dp++) {
                int dcol = (dh * 4 + dp) * 8 + g;
                int swz = dcol ^ (c << 3);
                uint32_t o0 = (8 * J + c) * 64 + swz;
                uint32_t o1 = (8 * J + c + 4) * 64 + swz;
                uint32_t bc0 = smu[bb + o0];
                uint32_t bc1 = smu[bb + o1];
                uint32_t bf0 = smu[bb + 1024 + o0];
                uint32_t bf1 = smu[bb + 1024 + o1];
                #pragma unroll
                for (int grp = 0; grp < 2; grp++) {
                    mma_f16(accA[grp][dp], Aa[grp][0][0], Aa[grp][0][1],
                            Aa[grp][1][0], Aa[grp][1][1], bc0, bc1);
                    mma_f16(accW[grp][dp], Ww[grp][0][0], Ww[grp][0][1],
                            Ww[grp][1][0], Ww[grp][1][1], bf0, bf1);
                }
            }
        }
    }

    // anti row sums: sw = 2048 + sum(wm1); SumV correction on accW
    int sbvf = (s * 2 + n) * 8 + h;
    #pragma unroll
    for (int grp = 0; grp < 2; grp++) {
        float s0 = sw0[grp], s1 = sw1[grp];
        s0 += __shfl_xor_sync(~0u, s0, 1);
        s0 += __shfl_xor_sync(~0u, s0, 2);
        s1 += __shfl_xor_sync(~0u, s1, 1);
        s1 += __shfl_xor_sync(~0u, s1, 2);
        float iw0 = (1.f - spv) / (2048.f + s0);
        float iw1 = (1.f - spv) / (2048.f + s1);
        int r = qt * 128 + rq * 32 + grp * 16 + g;
        #pragma unroll
        for (int dp = 0; dp < 4; dp++) {
            int colb = (dh * 4 + dp) * 8 + 2 * c;
            float2 sv = *(const float2*)&g_sv[sbvf][colb];
            int col = h * 64 + colb;
            *(float2*)&ob[(n * T_ + r) * D_ + col] =
                make_float2(spv * accA[grp][dp][0] + iw0 * (sv.x + accW[grp][dp][0]),
                            spv * accA[grp][dp][1] + iw0 * (sv.y + accW[grp][dp][1]));
            *(float2*)&ob[(n * T_ + r + 8) * D_ + col] =
                make_float2(spv * accA[grp][dp][2] + iw1 * (sv.x + accW[grp][dp][2]),
                            spv * accA[grp][dp][3] + iw1 * (sv.y + accW[grp][dp][3]));
        }
    }
}

// ---------------------------------------------------------------------------
extern "C" void kernel_launch(void* const* d_in, const int* in_sizes, int n_in,
                              void* d_out, int out_size) {
    const float* x   = (const float*)d_in[0];
    const float* y   = (const float*)d_in[1];
    const float* iw  = (const float*)d_in[2];
    const float* lw  = (const float*)d_in[3];
    const float* isc = (const float*)d_in[4];
    const float* lsc = (const float*)d_in[5];
    const float* sp  = (const float*)d_in[6];
    float* out = (float*)d_out;

    const int ATTN_SMEM = SMEM_WORDS * 4;   // 50176 bytes
    cudaFuncSetAttribute(attn_kernel, cudaFuncAttributeMaxDynamicSharedMemorySize, ATTN_SMEM);

    scale_kernel<<<1, 32>>>(isc, lsc);

    dim3 gq(1536 / 64, 4096 / 128, 2);
    qkv_tf32_kernel<<<gq, 256>>>(x, y, iw, lw);

    sumv_kernel<<<32, 256>>>();

    dim3 g2(T_ / 128, H_, 4);
    attn_kernel<<<g2, 256, ATTN_SMEM>>>(sp, out);
}